// round 8
// baseline (speedup 1.0000x reference)
#include <cuda_runtime.h>

typedef unsigned long long ull;

#define THREADS 512
#define TABLE_FLOATS (7 * 4096)              // j-major coefficient table (112 KB)
#define RED_FLOATS   (3 * 128 * 15)          // 3 quarters x 128 elem-slots x 15 (pad)
#define SMEM_BYTES   ((TABLE_FLOATS + RED_FLOATS) * 4)   // 137728 B

__device__ __forceinline__ ull pack2(float lo, float hi) {
    ull r; asm("mov.b64 %0, {%1, %2};" : "=l"(r) : "f"(lo), "f"(hi)); return r;
}
__device__ __forceinline__ void unpack2(ull v, float& lo, float& hi) {
    asm("mov.b64 {%0, %1}, %2;" : "=f"(lo), "=f"(hi) : "l"(v));
}
__device__ __forceinline__ ull mul2(ull a, ull b) {
    ull d; asm("mul.rn.f32x2 %0, %1, %2;" : "=l"(d) : "l"(a), "l"(b)); return d;
}
__device__ __forceinline__ ull fma2(ull a, ull b, ull c) {
    ull d; asm("fma.rn.f32x2 %0, %1, %2, %3;" : "=l"(d) : "l"(a), "l"(b), "l"(c)); return d;
}

// ANFIS restructured:
//   den[b] = prod_i (sum_t mu[b,i,t])
//   G[b,j] = sum_r w[b,r] * C[r,j]
//   out[b] = (sum_j xa[b,j] * G[b,j]) / (den[b] + 1e-8)
// Hybrid SIMD orientation: f32x2 packs RULE PAIRS, so the (c.x,c.y)/(c.z,c.w)
// halves of each float4 table load are directly usable as fma2 operands (zero
// duplication MOVs). Each thread carries TWO batch elements scalar-wise to
// amortize the broadcast LDS over 4 fma2 each. The w-chain uses duplicated
// membership pairs kept in registers.
// 16 warps/block: quarter = warp>>2 fixes d0; 4 warps x 32 lanes x 2 elements
// cover 256 elements per block. Quarter partials combined via smem staging.
__global__ void __launch_bounds__(THREADS, 1) anfis_kernel(
    const float* __restrict__ x,
    const float* __restrict__ centers,
    const float* __restrict__ sigmas,
    const float* __restrict__ cons,
    float* __restrict__ out)
{
    extern __shared__ float sm[];
    float* red = sm + TABLE_FLOATS;

    // --- Build j-major table: sm[j*4096 + r] = cons[r*7 + j] ---
    for (int idx = threadIdx.x; idx < TABLE_FLOATS; idx += THREADS) {
        int j = idx >> 12;
        int r = idx & 4095;
        sm[idx] = cons[r * 7 + j];
    }

    int lane = threadIdx.x & 31;
    int warp = threadIdx.x >> 5;
    int qtr  = warp >> 2;             // 0..3: fixed level-0 digit d0
    int wq   = warp & 3;
    int e    = wq * 32 + lane;        // element slot 0..127
    int b0   = blockIdx.x * 256 + e;
    int b1   = b0 + 128;

    // --- Memberships for 2 elements, duplicated f32x2 pairs ---
    ull A0_0 = 0, A0_1 = 0;           // mu0[qtr] duplicated
    ull m1_0[4], m1_1[4];             // level 1 (rolled loop -> local ok)
    ull m2_0[4], m2_1[4];             // level 2 (rolled loop -> local ok)
    ull m3_0[4], m3_1[4];             // level 3 (registers, unrolled idx)
    ull m4_0[4], m4_1[4];             // level 4 (registers, unrolled idx)
    ull p01_0, p23_0, p01_1, p23_1;   // level 5 natural pairs
    float m5v0[4], m5v1[4];
    float den0 = 1.0f, den1 = 1.0f;

#pragma unroll
    for (int i = 0; i < 6; i++) {
        float xa0 = x[b0 * 6 + i];
        float xa1 = x[b1 * 6 + i];
        float s0 = 0.0f, s1 = 0.0f;
#pragma unroll
        for (int t = 0; t < 4; t++) {
            float c   = centers[i * 4 + t];
            float sg  = fabsf(sigmas[i * 4 + t]) + 1e-6f;
            float inv = 0.5f / (sg * sg);
            float e0 = xa0 - c, e1 = xa1 - c;
            float v0 = __expf(-e0 * e0 * inv);
            float v1 = __expf(-e1 * e1 * inv);
            s0 += v0; s1 += v1;
            if (i == 0) { if (t == qtr) { A0_0 = pack2(v0, v0); A0_1 = pack2(v1, v1); } }
            else if (i == 1) { m1_0[t] = pack2(v0, v0); m1_1[t] = pack2(v1, v1); }
            else if (i == 2) { m2_0[t] = pack2(v0, v0); m2_1[t] = pack2(v1, v1); }
            else if (i == 3) { m3_0[t] = pack2(v0, v0); m3_1[t] = pack2(v1, v1); }
            else if (i == 4) { m4_0[t] = pack2(v0, v0); m4_1[t] = pack2(v1, v1); }
            else             { m5v0[t] = v0; m5v1[t] = v1; }
        }
        den0 *= s0; den1 *= s1;
    }
    p01_0 = pack2(m5v0[0], m5v0[1]);
    p23_0 = pack2(m5v0[2], m5v0[3]);
    p01_1 = pack2(m5v1[0], m5v1[1]);
    p23_1 = pack2(m5v1[2], m5v1[3]);
    __syncthreads();

    const float4* C4 = (const float4*)sm;   // C4[j*1024 + quadIdx]

    ull acc0[7], acc1[7];
#pragma unroll
    for (int j = 0; j < 7; j++) { acc0[j] = 0; acc1[j] = 0; }

#pragma unroll 1
    for (int d1 = 0; d1 < 4; d1++) {
        ull A1_0 = mul2(A0_0, m1_0[d1]);
        ull A1_1 = mul2(A0_1, m1_1[d1]);
#pragma unroll 1
        for (int d2 = 0; d2 < 4; d2++) {
            ull A2_0 = mul2(A1_0, m2_0[d2]);
            ull A2_1 = mul2(A1_1, m2_1[d2]);
            int qb = qtr * 256 + d1 * 64 + d2 * 16;
#pragma unroll
            for (int d3 = 0; d3 < 4; d3++) {
                ull A3_0 = mul2(A2_0, m3_0[d3]);
                ull A3_1 = mul2(A2_1, m3_1[d3]);
#pragma unroll
                for (int d4 = 0; d4 < 4; d4++) {
                    ull A4_0 = mul2(A3_0, m4_0[d4]);
                    ull A4_1 = mul2(A3_1, m4_1[d4]);
                    ull w01_0 = mul2(A4_0, p01_0);
                    ull w23_0 = mul2(A4_0, p23_0);
                    ull w01_1 = mul2(A4_1, p01_1);
                    ull w23_1 = mul2(A4_1, p23_1);
                    int qq = qb + d3 * 4 + d4;
#pragma unroll
                    for (int j = 0; j < 7; j++) {
                        float4 c = C4[j * 1024 + qq];
                        ull cA = pack2(c.x, c.y);   // consecutive regs: no MOV
                        ull cB = pack2(c.z, c.w);
                        acc0[j] = fma2(w01_0, cA, acc0[j]);
                        acc1[j] = fma2(w01_1, cA, acc1[j]);
                        acc0[j] = fma2(w23_0, cB, acc0[j]);
                        acc1[j] = fma2(w23_1, cB, acc1[j]);
                    }
                }
            }
        }
    }

    // --- Collapse rule pairs: g = lo + hi ---
    float g0[7], g1[7];
#pragma unroll
    for (int j = 0; j < 7; j++) {
        float lo, hi;
        unpack2(acc0[j], lo, hi); g0[j] = lo + hi;
        unpack2(acc1[j], lo, hi); g1[j] = lo + hi;
    }

    // --- Combine 4 rule-quarters via smem staging (stride 15: conflict-free) ---
    if (qtr != 0) {
        float* base = red + ((qtr - 1) * 128 + e) * 15;
#pragma unroll
        for (int j = 0; j < 7; j++) {
            base[j]     = g0[j];
            base[7 + j] = g1[j];
        }
    }
    __syncthreads();

    if (qtr == 0) {
#pragma unroll 1
        for (int o = 0; o < 3; o++) {
            const float* base = red + (o * 128 + e) * 15;
#pragma unroll
            for (int j = 0; j < 7; j++) {
                g0[j] += base[j];
                g1[j] += base[7 + j];
            }
        }
        float n0 = g0[6], n1 = g1[6];
#pragma unroll
        for (int i = 0; i < 6; i++) {
            n0 += g0[i] * x[b0 * 6 + i];
            n1 += g1[i] * x[b1 * 6 + i];
        }
        out[b0] = n0 / (den0 + 1e-8f);
        out[b1] = n1 / (den1 + 1e-8f);
    }
}

extern "C" void kernel_launch(void* const* d_in, const int* in_sizes, int n_in,
                              void* d_out, int out_size) {
    const float* x       = (const float*)d_in[0];
    const float* centers = (const float*)d_in[1];
    const float* sigmas  = (const float*)d_in[2];
    const float* cons    = (const float*)d_in[3];
    float* out = (float*)d_out;

    int B = in_sizes[0] / 6;        // 32768
    int blocks = B / 256;           // 128

    cudaFuncSetAttribute(anfis_kernel,
                         cudaFuncAttributeMaxDynamicSharedMemorySize, SMEM_BYTES);

    anfis_kernel<<<blocks, THREADS, SMEM_BYTES>>>(x, centers, sigmas, cons, out);
}